// round 2
// baseline (speedup 1.0000x reference)
#include <cuda_runtime.h>

// Problem constants (fixed by the dataset): B=2, L=2048, D=1024, H=16, d=64
#define L_SEQ   2048
#define D_MODEL 1024
#define NHEADS  16
#define DHEAD   64
#define CHUNK   64
#define NCHUNK  32              // L / CHUNK
#define MROWS   4096            // B * L
#define TRIPLE  3072            // 3 * D

// Scratch: device globals, referenced directly inside kernels (NO
// cudaGetSymbolAddress / no runtime API in kernel_launch besides launches).
__device__ float g_qkv[(size_t)MROWS * TRIPLE];            // [B*L, 3D]
__device__ float g_kv [(size_t)1024 * 4096];               // [B*H*NC, 64*64]
__device__ float g_y  [(size_t)MROWS * D_MODEL];           // [B*L, D]

// ---------------------------------------------------------------------------
// SGEMM (NT): C[M,N] = A[M,K] @ B[N,K]^T + bias[N]
// 128x128 block tile, BK=16, 256 threads, 8x8 microtile (split 4+4 halves).
// ---------------------------------------------------------------------------
__global__ __launch_bounds__(256) void sgemm_nt_bias(
    const float* __restrict__ A, const float* __restrict__ B,
    const float* __restrict__ bias, float* __restrict__ C,
    int M, int N, int K)
{
    __shared__ float As[16][128];   // transposed: As[k][m]
    __shared__ float Bs[16][128];   // transposed: Bs[k][n]

    const int tid = threadIdx.x;
    const int m0  = blockIdx.y * 128;
    const int n0  = blockIdx.x * 128;
    const int tx  = tid & 15;       // 0..15 -> n micro group
    const int ty  = tid >> 4;       // 0..15 -> m micro group
    const int lr  = tid >> 2;       // 0..63 load row
    const int lc  = tid & 3;        // 0..3 float4 within 16-wide K slab

    float acc[8][8];
    #pragma unroll
    for (int i = 0; i < 8; i++)
        #pragma unroll
        for (int j = 0; j < 8; j++) acc[i][j] = 0.f;

    const float* Ag = A + (size_t)(m0 + lr) * K + lc * 4;
    const float* Bg = B + (size_t)(n0 + lr) * K + lc * 4;

    for (int k0 = 0; k0 < K; k0 += 16) {
        #pragma unroll
        for (int half = 0; half < 2; half++) {
            int row = lr + half * 64;
            float4 a4 = *(const float4*)(Ag + (size_t)half * 64 * K + k0);
            float4 b4 = *(const float4*)(Bg + (size_t)half * 64 * K + k0);
            As[lc*4+0][row] = a4.x; As[lc*4+1][row] = a4.y;
            As[lc*4+2][row] = a4.z; As[lc*4+3][row] = a4.w;
            Bs[lc*4+0][row] = b4.x; Bs[lc*4+1][row] = b4.y;
            Bs[lc*4+2][row] = b4.z; Bs[lc*4+3][row] = b4.w;
        }
        __syncthreads();
        #pragma unroll
        for (int kk = 0; kk < 16; kk++) {
            float a[8], b[8];
            *(float4*)(a)     = *(const float4*)&As[kk][ty*4];
            *(float4*)(a + 4) = *(const float4*)&As[kk][64 + ty*4];
            *(float4*)(b)     = *(const float4*)&Bs[kk][tx*4];
            *(float4*)(b + 4) = *(const float4*)&Bs[kk][64 + tx*4];
            #pragma unroll
            for (int i = 0; i < 8; i++)
                #pragma unroll
                for (int j = 0; j < 8; j++)
                    acc[i][j] = fmaf(a[i], b[j], acc[i][j]);
        }
        __syncthreads();
    }

    #pragma unroll
    for (int ih = 0; ih < 2; ih++)
        #pragma unroll
        for (int ii = 0; ii < 4; ii++) {
            int row = m0 + ih*64 + ty*4 + ii;
            #pragma unroll
            for (int jh = 0; jh < 2; jh++) {
                int col = n0 + jh*64 + tx*4;
                float4 o;
                o.x = acc[ih*4+ii][jh*4+0] + bias[col+0];
                o.y = acc[ih*4+ii][jh*4+1] + bias[col+1];
                o.z = acc[ih*4+ii][jh*4+2] + bias[col+2];
                o.w = acc[ih*4+ii][jh*4+3] + bias[col+3];
                *(float4*)(C + (size_t)row * N + col) = o;
            }
        }
}

// Variant writing into the g_qkv scratch (first GEMM).
__global__ __launch_bounds__(256) void sgemm_qkv(
    const float* __restrict__ A, const float* __restrict__ B,
    const float* __restrict__ bias)
{
    // Delegate pattern is identical; inline the body via a device call would
    // duplicate code — instead just call with g_qkv as C. (Device globals are
    // valid pointers inside kernels.)
    // NOTE: implemented as a thin wrapper: compute into g_qkv.
    // -- body duplicated from sgemm_nt_bias with C = g_qkv, M/N/K fixed --
    const int M = MROWS, N = TRIPLE, K = D_MODEL;
    float* C = g_qkv;

    __shared__ float As[16][128];
    __shared__ float Bs[16][128];

    const int tid = threadIdx.x;
    const int m0  = blockIdx.y * 128;
    const int n0  = blockIdx.x * 128;
    const int tx  = tid & 15;
    const int ty  = tid >> 4;
    const int lr  = tid >> 2;
    const int lc  = tid & 3;

    float acc[8][8];
    #pragma unroll
    for (int i = 0; i < 8; i++)
        #pragma unroll
        for (int j = 0; j < 8; j++) acc[i][j] = 0.f;

    const float* Ag = A + (size_t)(m0 + lr) * K + lc * 4;
    const float* Bg = B + (size_t)(n0 + lr) * K + lc * 4;

    for (int k0 = 0; k0 < K; k0 += 16) {
        #pragma unroll
        for (int half = 0; half < 2; half++) {
            int row = lr + half * 64;
            float4 a4 = *(const float4*)(Ag + (size_t)half * 64 * K + k0);
            float4 b4 = *(const float4*)(Bg + (size_t)half * 64 * K + k0);
            As[lc*4+0][row] = a4.x; As[lc*4+1][row] = a4.y;
            As[lc*4+2][row] = a4.z; As[lc*4+3][row] = a4.w;
            Bs[lc*4+0][row] = b4.x; Bs[lc*4+1][row] = b4.y;
            Bs[lc*4+2][row] = b4.z; Bs[lc*4+3][row] = b4.w;
        }
        __syncthreads();
        #pragma unroll
        for (int kk = 0; kk < 16; kk++) {
            float a[8], b[8];
            *(float4*)(a)     = *(const float4*)&As[kk][ty*4];
            *(float4*)(a + 4) = *(const float4*)&As[kk][64 + ty*4];
            *(float4*)(b)     = *(const float4*)&Bs[kk][tx*4];
            *(float4*)(b + 4) = *(const float4*)&Bs[kk][64 + tx*4];
            #pragma unroll
            for (int i = 0; i < 8; i++)
                #pragma unroll
                for (int j = 0; j < 8; j++)
                    acc[i][j] = fmaf(a[i], b[j], acc[i][j]);
        }
        __syncthreads();
    }

    #pragma unroll
    for (int ih = 0; ih < 2; ih++)
        #pragma unroll
        for (int ii = 0; ii < 4; ii++) {
            int row = m0 + ih*64 + ty*4 + ii;
            #pragma unroll
            for (int jh = 0; jh < 2; jh++) {
                int col = n0 + jh*64 + tx*4;
                float4 o;
                o.x = acc[ih*4+ii][jh*4+0] + bias[col+0];
                o.y = acc[ih*4+ii][jh*4+1] + bias[col+1];
                o.z = acc[ih*4+ii][jh*4+2] + bias[col+2];
                o.w = acc[ih*4+ii][jh*4+3] + bias[col+3];
                *(float4*)(C + (size_t)row * N + col) = o;
            }
        }
}

// Final GEMM: out = g_y @ out_w^T + out_b, reads A from g_y.
__global__ __launch_bounds__(256) void sgemm_out(
    const float* __restrict__ B, const float* __restrict__ bias,
    float* __restrict__ C)
{
    const int M = MROWS, N = D_MODEL, K = D_MODEL;
    const float* A = g_y;

    __shared__ float As[16][128];
    __shared__ float Bs[16][128];

    const int tid = threadIdx.x;
    const int m0  = blockIdx.y * 128;
    const int n0  = blockIdx.x * 128;
    const int tx  = tid & 15;
    const int ty  = tid >> 4;
    const int lr  = tid >> 2;
    const int lc  = tid & 3;

    float acc[8][8];
    #pragma unroll
    for (int i = 0; i < 8; i++)
        #pragma unroll
        for (int j = 0; j < 8; j++) acc[i][j] = 0.f;

    const float* Ag = A + (size_t)(m0 + lr) * K + lc * 4;
    const float* Bg = B + (size_t)(n0 + lr) * K + lc * 4;

    for (int k0 = 0; k0 < K; k0 += 16) {
        #pragma unroll
        for (int half = 0; half < 2; half++) {
            int row = lr + half * 64;
            float4 a4 = *(const float4*)(Ag + (size_t)half * 64 * K + k0);
            float4 b4 = *(const float4*)(Bg + (size_t)half * 64 * K + k0);
            As[lc*4+0][row] = a4.x; As[lc*4+1][row] = a4.y;
            As[lc*4+2][row] = a4.z; As[lc*4+3][row] = a4.w;
            Bs[lc*4+0][row] = b4.x; Bs[lc*4+1][row] = b4.y;
            Bs[lc*4+2][row] = b4.z; Bs[lc*4+3][row] = b4.w;
        }
        __syncthreads();
        #pragma unroll
        for (int kk = 0; kk < 16; kk++) {
            float a[8], b[8];
            *(float4*)(a)     = *(const float4*)&As[kk][ty*4];
            *(float4*)(a + 4) = *(const float4*)&As[kk][64 + ty*4];
            *(float4*)(b)     = *(const float4*)&Bs[kk][tx*4];
            *(float4*)(b + 4) = *(const float4*)&Bs[kk][64 + tx*4];
            #pragma unroll
            for (int i = 0; i < 8; i++)
                #pragma unroll
                for (int j = 0; j < 8; j++)
                    acc[i][j] = fmaf(a[i], b[j], acc[i][j]);
        }
        __syncthreads();
    }

    #pragma unroll
    for (int ih = 0; ih < 2; ih++)
        #pragma unroll
        for (int ii = 0; ii < 4; ii++) {
            int row = m0 + ih*64 + ty*4 + ii;
            #pragma unroll
            for (int jh = 0; jh < 2; jh++) {
                int col = n0 + jh*64 + tx*4;
                float4 o;
                o.x = acc[ih*4+ii][jh*4+0] + bias[col+0];
                o.y = acc[ih*4+ii][jh*4+1] + bias[col+1];
                o.z = acc[ih*4+ii][jh*4+2] + bias[col+2];
                o.w = acc[ih*4+ii][jh*4+3] + bias[col+3];
                *(float4*)(C + (size_t)row * N + col) = o;
            }
        }
}

// ---------------------------------------------------------------------------
// Per-(b,h,chunk): KV = K_c^T V_c  (64x64), K pre-scaled by 1/sqrt(d)=0.125
// ---------------------------------------------------------------------------
__global__ __launch_bounds__(256) void chunk_kv_kernel()
{
    __shared__ float Ks[64][64];
    __shared__ float Vs[64][64];
    const int blk = blockIdx.x;            // bh*32 + c
    const int c   = blk & 31;
    const int bh  = blk >> 5;
    const int h   = bh & 15;
    const int b   = bh >> 4;
    const int tid = threadIdx.x;
    const int t0g = c * CHUNK;

    for (int idx = tid; idx < 64*16; idx += 256) {
        int r = idx >> 4, c4 = idx & 15;
        size_t base = ((size_t)(b*L_SEQ + t0g + r)) * TRIPLE + h*DHEAD + c4*4;
        float4 k4 = *(const float4*)(g_qkv + base + 1024);
        float4 v4 = *(const float4*)(g_qkv + base + 2048);
        k4.x *= 0.125f; k4.y *= 0.125f; k4.z *= 0.125f; k4.w *= 0.125f;
        *(float4*)&Ks[r][c4*4] = k4;
        *(float4*)&Vs[r][c4*4] = v4;
    }
    __syncthreads();

    const int i0 = (tid >> 4) * 4;
    const int j0 = (tid & 15) * 4;
    float acc[4][4] = {};
    #pragma unroll 8
    for (int t = 0; t < 64; t++) {
        float k4[4], v4[4];
        *(float4*)k4 = *(const float4*)&Ks[t][i0];
        *(float4*)v4 = *(const float4*)&Vs[t][j0];
        #pragma unroll
        for (int ii = 0; ii < 4; ii++)
            #pragma unroll
            for (int jj = 0; jj < 4; jj++)
                acc[ii][jj] = fmaf(k4[ii], v4[jj], acc[ii][jj]);
    }
    float* outp = g_kv + (size_t)blk * 4096;
    #pragma unroll
    for (int ii = 0; ii < 4; ii++)
        *(float4*)(outp + (i0+ii)*64 + j0) =
            make_float4(acc[ii][0], acc[ii][1], acc[ii][2], acc[ii][3]);
}

// ---------------------------------------------------------------------------
// In-place exclusive prefix over chunks: S_c = sum_{c'<c} KV_{c'}
// One block per (b,h); each thread owns 16 of the 4096 state elements.
// ---------------------------------------------------------------------------
__global__ __launch_bounds__(256) void prefix_kernel()
{
    const int bh = blockIdx.x;
    const size_t base0 = (size_t)bh * NCHUNK * 4096;
    for (int e = threadIdx.x; e < 4096; e += 256) {
        float run = 0.f;
        size_t base = base0 + e;
        #pragma unroll
        for (int c = 0; c < NCHUNK; c++) {
            float t = g_kv[base + (size_t)c * 4096];
            g_kv[base + (size_t)c * 4096] = run;
            run += t;
        }
    }
}

// ---------------------------------------------------------------------------
// Per-(b,h,chunk) output: y = Q @ S + (Q K^T (.) tril) @ V
// 48 KB static smem: Qs transposed [i][t]; Bs time-multiplexed S -> K^T -> V;
// Ps stored [s][t].
// ---------------------------------------------------------------------------
__global__ __launch_bounds__(256) void chunk_out_kernel()
{
    __shared__ float Qs[64][64];   // Qs[i][t]  (transposed)
    __shared__ float Bs[64][64];   // S natural -> K^T [i][s] -> V natural
    __shared__ float Ps[64][64];   // Ps[s][t]

    const int blk = blockIdx.x;
    const int c   = blk & 31;
    const int bh  = blk >> 5;
    const int h   = bh & 15;
    const int b   = bh >> 4;
    const int tid = threadIdx.x;
    const int t0  = (tid >> 4) * 4;   // rows (t for y, s for P)
    const int j0  = (tid & 15) * 4;   // cols (j for y, t for P)
    const int ct0 = c * CHUNK;

    // Load Q (transposed) and S (natural)
    for (int idx = tid; idx < 64*16; idx += 256) {
        int r = idx >> 4, c4 = idx & 15;
        size_t base = ((size_t)(b*L_SEQ + ct0 + r)) * TRIPLE + h*DHEAD + c4*4;
        float4 q4 = *(const float4*)(g_qkv + base);
        Qs[c4*4+0][r] = q4.x; Qs[c4*4+1][r] = q4.y;
        Qs[c4*4+2][r] = q4.z; Qs[c4*4+3][r] = q4.w;
        *(float4*)&Bs[r][c4*4] =
            *(const float4*)(g_kv + (size_t)blk * 4096 + r*64 + c4*4);
    }
    __syncthreads();

    // y(acc) = Q @ S
    float acc[4][4] = {};
    #pragma unroll 8
    for (int i = 0; i < 64; i++) {
        float q4[4], s4[4];
        *(float4*)q4 = *(const float4*)&Qs[i][t0];
        *(float4*)s4 = *(const float4*)&Bs[i][j0];
        #pragma unroll
        for (int tt = 0; tt < 4; tt++)
            #pragma unroll
            for (int jj = 0; jj < 4; jj++)
                acc[tt][jj] = fmaf(q4[tt], s4[jj], acc[tt][jj]);
    }
    __syncthreads();

    // Load K (scaled, transposed into Bs[i][s])
    for (int idx = tid; idx < 64*16; idx += 256) {
        int r = idx >> 4, c4 = idx & 15;
        size_t base = ((size_t)(b*L_SEQ + ct0 + r)) * TRIPLE + 1024 + h*DHEAD + c4*4;
        float4 k4 = *(const float4*)(g_qkv + base);
        Bs[c4*4+0][r] = k4.x * 0.125f; Bs[c4*4+1][r] = k4.y * 0.125f;
        Bs[c4*4+2][r] = k4.z * 0.125f; Bs[c4*4+3][r] = k4.w * 0.125f;
    }
    __syncthreads();

    // P[s][t] = sum_i K[s][i] Q[t][i], masked t>=s. Thread: s in t0.., t in j0..
    {
        float pacc[4][4] = {};
        #pragma unroll 8
        for (int i = 0; i < 64; i++) {
            float k4[4], q4[4];
            *(float4*)k4 = *(const float4*)&Bs[i][t0];   // K^T: [i][s]
            *(float4*)q4 = *(const float4*)&Qs[i][j0];   // Q^T: [i][t]
            #pragma unroll
            for (int ss = 0; ss < 4; ss++)
                #pragma unroll
                for (int tt = 0; tt < 4; tt++)
                    pacc[ss][tt] = fmaf(k4[ss], q4[tt], pacc[ss][tt]);
        }
        #pragma unroll
        for (int ss = 0; ss < 4; ss++) {
            int s = t0 + ss;
            float4 o;
            o.x = (j0+0 >= s) ? pacc[ss][0] : 0.f;
            o.y = (j0+1 >= s) ? pacc[ss][1] : 0.f;
            o.z = (j0+2 >= s) ? pacc[ss][2] : 0.f;
            o.w = (j0+3 >= s) ? pacc[ss][3] : 0.f;
            *(float4*)&Ps[s][j0] = o;
        }
    }
    __syncthreads();

    // Load V (natural) over Bs
    for (int idx = tid; idx < 64*16; idx += 256) {
        int r = idx >> 4, c4 = idx & 15;
        size_t base = ((size_t)(b*L_SEQ + ct0 + r)) * TRIPLE + 2048 + h*DHEAD + c4*4;
        *(float4*)&Bs[r][c4*4] = *(const float4*)(g_qkv + base);
    }
    __syncthreads();

    // y(acc) += P @ V   (P[t][s] = Ps[s][t])
    #pragma unroll 8
    for (int s = 0; s < 64; s++) {
        float p4[4], v4[4];
        *(float4*)p4 = *(const float4*)&Ps[s][t0];
        *(float4*)v4 = *(const float4*)&Bs[s][j0];
        #pragma unroll
        for (int tt = 0; tt < 4; tt++)
            #pragma unroll
            for (int jj = 0; jj < 4; jj++)
                acc[tt][jj] = fmaf(p4[tt], v4[jj], acc[tt][jj]);
    }

    // Store y[b, t, h*64 + j]
    #pragma unroll
    for (int tt = 0; tt < 4; tt++) {
        size_t row = (size_t)(b*L_SEQ + ct0 + t0 + tt);
        *(float4*)(g_y + row * D_MODEL + h*DHEAD + j0) =
            make_float4(acc[tt][0], acc[tt][1], acc[tt][2], acc[tt][3]);
    }
}

// ---------------------------------------------------------------------------
extern "C" void kernel_launch(void* const* d_in, const int* in_sizes, int n_in,
                              void* d_out, int out_size)
{
    const float* x      = (const float*)d_in[0];
    const float* Wqkv_w = (const float*)d_in[1];
    const float* Wqkv_b = (const float*)d_in[2];
    const float* out_w  = (const float*)d_in[3];
    const float* out_b  = (const float*)d_in[4];
    float* out = (float*)d_out;

    // 1) QKV projection: g_qkv[4096,3072] = x @ Wqkv_w^T + b
    sgemm_qkv<<<dim3(TRIPLE/128, MROWS/128), 256>>>(x, Wqkv_w, Wqkv_b);

    // 2) Per-chunk KV = K^T V
    chunk_kv_kernel<<<1024, 256>>>();

    // 3) Exclusive prefix over chunks -> inter-chunk states S
    prefix_kernel<<<32, 256>>>();

    // 4) Per-chunk output: y = Q S + (Q K^T . tril) V
    chunk_out_kernel<<<1024, 256>>>();

    // 5) Output projection: out[4096,1024] = g_y @ out_w^T + b
    sgemm_out<<<dim3(D_MODEL/128, MROWS/128), 256>>>(out_w, out_b, out);
}

// round 3
// speedup vs baseline: 1.6478x; 1.6478x over previous
#include <cuda_runtime.h>
#include <cuda_bf16.h>
#include <cstdint>

// Problem constants: B=2, L=2048, D=1024, H=16, d=64
#define L_SEQ   2048
#define D_MODEL 1024
#define NHEADS  16
#define DHEAD   64
#define CHUNK   64
#define NCHUNK  32
#define MROWS   4096            // B * L
#define TRIPLE  3072            // 3 * D

// fp32 scratch
__device__ float g_qkv[(size_t)MROWS * TRIPLE];            // [B*L, 3D]
__device__ float g_kv [(size_t)1024 * 4096];               // [B*H*NC, 64*64]
__device__ float g_y  [(size_t)MROWS * D_MODEL];           // [B*L, D]

// bf16 split planes
__device__ __nv_bfloat16 g_xh[(size_t)MROWS * D_MODEL];
__device__ __nv_bfloat16 g_xl[(size_t)MROWS * D_MODEL];
__device__ __nv_bfloat16 g_wh[(size_t)TRIPLE * D_MODEL];
__device__ __nv_bfloat16 g_wl[(size_t)TRIPLE * D_MODEL];
__device__ __nv_bfloat16 g_yh[(size_t)MROWS * D_MODEL];
__device__ __nv_bfloat16 g_yl[(size_t)MROWS * D_MODEL];
__device__ __nv_bfloat16 g_owh[(size_t)D_MODEL * D_MODEL];
__device__ __nv_bfloat16 g_owl[(size_t)D_MODEL * D_MODEL];

// ---------------------------------------------------------------------------
// fp32 -> (bf16 hi, bf16 lo) split conversion, float4-vectorized.
// ---------------------------------------------------------------------------
__device__ __forceinline__ void cvt_body(const float* __restrict__ in,
                                         __nv_bfloat16* __restrict__ hi,
                                         __nv_bfloat16* __restrict__ lo,
                                         int n4)
{
    int i = blockIdx.x * blockDim.x + threadIdx.x;
    if (i >= n4) return;
    float4 v = ((const float4*)in)[i];
    __nv_bfloat16 h0 = __float2bfloat16(v.x);
    __nv_bfloat16 h1 = __float2bfloat16(v.y);
    __nv_bfloat16 h2 = __float2bfloat16(v.z);
    __nv_bfloat16 h3 = __float2bfloat16(v.w);
    __nv_bfloat162 hh0; hh0.x = h0; hh0.y = h1;
    __nv_bfloat162 hh1; hh1.x = h2; hh1.y = h3;
    __nv_bfloat162 ll0, ll1;
    ll0.x = __float2bfloat16(v.x - __bfloat162float(h0));
    ll0.y = __float2bfloat16(v.y - __bfloat162float(h1));
    ll1.x = __float2bfloat16(v.z - __bfloat162float(h2));
    ll1.y = __float2bfloat16(v.w - __bfloat162float(h3));
    ((__nv_bfloat162*)hi)[i*2+0] = hh0;
    ((__nv_bfloat162*)hi)[i*2+1] = hh1;
    ((__nv_bfloat162*)lo)[i*2+0] = ll0;
    ((__nv_bfloat162*)lo)[i*2+1] = ll1;
}

__global__ void cvt_x   (const float* __restrict__ in) { cvt_body(in,  g_xh,  g_xl,  MROWS*D_MODEL/4); }
__global__ void cvt_w   (const float* __restrict__ in) { cvt_body(in,  g_wh,  g_wl,  TRIPLE*D_MODEL/4); }
__global__ void cvt_y   ()                             { cvt_body(g_y, g_yh,  g_yl,  MROWS*D_MODEL/4); }
__global__ void cvt_ow  (const float* __restrict__ in) { cvt_body(in,  g_owh, g_owl, D_MODEL*D_MODEL/4); }

// ---------------------------------------------------------------------------
// bf16-split tensor-core GEMM (NT): C[M,N] = A[M,K] @ B[N,K]^T + bias[N]
// A,B given as (hi, lo) bf16 planes; result in fp32 via 3 mma products.
// 128x128 block tile, BK=32, 256 threads, 8 warps (2x4), warp tile 64x32.
// ---------------------------------------------------------------------------
#define SP 40   // smem row stride in halves (padded, conflict-free for frags)

__device__ __forceinline__ void mma16816(float* d, const unsigned* a, const unsigned* b)
{
    asm volatile(
        "mma.sync.aligned.m16n8k16.row.col.f32.bf16.bf16.f32 "
        "{%0,%1,%2,%3}, {%4,%5,%6,%7}, {%8,%9}, {%0,%1,%2,%3};\n"
        : "+f"(d[0]), "+f"(d[1]), "+f"(d[2]), "+f"(d[3])
        : "r"(a[0]), "r"(a[1]), "r"(a[2]), "r"(a[3]), "r"(b[0]), "r"(b[1]));
}

template<int M, int N, int K>
__device__ __forceinline__ void gemm_body(
    const __nv_bfloat16* __restrict__ Ahi, const __nv_bfloat16* __restrict__ Alo,
    const __nv_bfloat16* __restrict__ Bhi, const __nv_bfloat16* __restrict__ Blo,
    const float* __restrict__ bias, float* __restrict__ C)
{
    __shared__ __nv_bfloat16 sAh[128*SP];
    __shared__ __nv_bfloat16 sAl[128*SP];
    __shared__ __nv_bfloat16 sBh[128*SP];
    __shared__ __nv_bfloat16 sBl[128*SP];

    const int tid  = threadIdx.x;
    const int warp = tid >> 5;
    const int lane = tid & 31;
    const int wm   = warp & 1;          // 0..1 -> 64-row half
    const int wn   = warp >> 1;         // 0..3 -> 32-col quarter
    const int g    = lane >> 2;         // 0..7
    const int t    = lane & 3;          // 0..3
    const int m0   = blockIdx.y * 128;
    const int n0   = blockIdx.x * 128;

    float acc[4][4][4];
    #pragma unroll
    for (int mt = 0; mt < 4; mt++)
        #pragma unroll
        for (int nt = 0; nt < 4; nt++)
            #pragma unroll
            for (int r = 0; r < 4; r++) acc[mt][nt][r] = 0.f;

    for (int k0 = 0; k0 < K; k0 += 32) {
        // ---- load tiles: 128 rows x 32 halves per plane, uint4 chunks ----
        #pragma unroll
        for (int p = 0; p < 2; p++) {
            int linear = tid + p*256;          // 0..511
            int row = linear >> 2;
            int q   = linear & 3;
            size_t ga = (size_t)(m0 + row) * K + k0 + q*8;
            size_t gb = (size_t)(n0 + row) * K + k0 + q*8;
            int so = row*SP + q*8;
            *(uint4*)&sAh[so] = *(const uint4*)&Ahi[ga];
            *(uint4*)&sAl[so] = *(const uint4*)&Alo[ga];
            *(uint4*)&sBh[so] = *(const uint4*)&Bhi[gb];
            *(uint4*)&sBl[so] = *(const uint4*)&Blo[gb];
        }
        __syncthreads();

        #pragma unroll
        for (int ks = 0; ks < 32; ks += 16) {
            unsigned ah[4][4], al[4][4], bh[4][2], bl[4][2];
            #pragma unroll
            for (int mt = 0; mt < 4; mt++) {
                int base = (wm*64 + mt*16 + g)*SP + ks + 2*t;
                ah[mt][0] = *(const unsigned*)&sAh[base];
                ah[mt][1] = *(const unsigned*)&sAh[base + 8*SP];
                ah[mt][2] = *(const unsigned*)&sAh[base + 8];
                ah[mt][3] = *(const unsigned*)&sAh[base + 8*SP + 8];
                al[mt][0] = *(const unsigned*)&sAl[base];
                al[mt][1] = *(const unsigned*)&sAl[base + 8*SP];
                al[mt][2] = *(const unsigned*)&sAl[base + 8];
                al[mt][3] = *(const unsigned*)&sAl[base + 8*SP + 8];
            }
            #pragma unroll
            for (int nt = 0; nt < 4; nt++) {
                int base = (wn*32 + nt*8 + g)*SP + ks + 2*t;
                bh[nt][0] = *(const unsigned*)&sBh[base];
                bh[nt][1] = *(const unsigned*)&sBh[base + 8];
                bl[nt][0] = *(const unsigned*)&sBl[base];
                bl[nt][1] = *(const unsigned*)&sBl[base + 8];
            }
            #pragma unroll
            for (int mt = 0; mt < 4; mt++)
                #pragma unroll
                for (int nt = 0; nt < 4; nt++) {
                    mma16816(acc[mt][nt], ah[mt], bh[nt]);  // hi*hi
                    mma16816(acc[mt][nt], ah[mt], bl[nt]);  // hi*lo
                    mma16816(acc[mt][nt], al[mt], bh[nt]);  // lo*hi
                }
        }
        __syncthreads();
    }

    // ---- epilogue: C[r][c] = acc + bias[c], float2 stores ----
    #pragma unroll
    for (int mt = 0; mt < 4; mt++) {
        int r = m0 + wm*64 + mt*16 + g;
        #pragma unroll
        for (int nt = 0; nt < 4; nt++) {
            int c = n0 + wn*32 + nt*8 + 2*t;
            float b0 = bias[c], b1 = bias[c+1];
            float2 o0 = make_float2(acc[mt][nt][0] + b0, acc[mt][nt][1] + b1);
            float2 o1 = make_float2(acc[mt][nt][2] + b0, acc[mt][nt][3] + b1);
            *(float2*)&C[(size_t)r * N + c]       = o0;
            *(float2*)&C[(size_t)(r+8) * N + c]   = o1;
        }
    }
}

__global__ __launch_bounds__(256,1) void gemm_qkv_bf16(const float* __restrict__ bias)
{
    gemm_body<MROWS, TRIPLE, D_MODEL>(g_xh, g_xl, g_wh, g_wl, bias, g_qkv);
}

__global__ __launch_bounds__(256,1) void gemm_out_bf16(const float* __restrict__ bias,
                                                       float* __restrict__ C)
{
    gemm_body<MROWS, D_MODEL, D_MODEL>(g_yh, g_yl, g_owh, g_owl, bias, C);
}

// ---------------------------------------------------------------------------
// Per-(b,h,chunk): KV = K_c^T V_c  (64x64), K pre-scaled by 1/sqrt(d)=0.125
// ---------------------------------------------------------------------------
__global__ __launch_bounds__(256) void chunk_kv_kernel()
{
    __shared__ float Ks[64][64];
    __shared__ float Vs[64][64];
    const int blk = blockIdx.x;            // bh*32 + c
    const int c   = blk & 31;
    const int bh  = blk >> 5;
    const int h   = bh & 15;
    const int b   = bh >> 4;
    const int tid = threadIdx.x;
    const int t0g = c * CHUNK;

    for (int idx = tid; idx < 64*16; idx += 256) {
        int r = idx >> 4, c4 = idx & 15;
        size_t base = ((size_t)(b*L_SEQ + t0g + r)) * TRIPLE + h*DHEAD + c4*4;
        float4 k4 = *(const float4*)(g_qkv + base + 1024);
        float4 v4 = *(const float4*)(g_qkv + base + 2048);
        k4.x *= 0.125f; k4.y *= 0.125f; k4.z *= 0.125f; k4.w *= 0.125f;
        *(float4*)&Ks[r][c4*4] = k4;
        *(float4*)&Vs[r][c4*4] = v4;
    }
    __syncthreads();

    const int i0 = (tid >> 4) * 4;
    const int j0 = (tid & 15) * 4;
    float acc[4][4] = {};
    #pragma unroll 8
    for (int t = 0; t < 64; t++) {
        float k4[4], v4[4];
        *(float4*)k4 = *(const float4*)&Ks[t][i0];
        *(float4*)v4 = *(const float4*)&Vs[t][j0];
        #pragma unroll
        for (int ii = 0; ii < 4; ii++)
            #pragma unroll
            for (int jj = 0; jj < 4; jj++)
                acc[ii][jj] = fmaf(k4[ii], v4[jj], acc[ii][jj]);
    }
    float* outp = g_kv + (size_t)blk * 4096;
    #pragma unroll
    for (int ii = 0; ii < 4; ii++)
        *(float4*)(outp + (i0+ii)*64 + j0) =
            make_float4(acc[ii][0], acc[ii][1], acc[ii][2], acc[ii][3]);
}

// ---------------------------------------------------------------------------
// In-place exclusive prefix over chunks: S_c = sum_{c'<c} KV_{c'}
// ---------------------------------------------------------------------------
__global__ __launch_bounds__(256) void prefix_kernel()
{
    const int bh = blockIdx.x;
    const size_t base0 = (size_t)bh * NCHUNK * 4096;
    for (int e = threadIdx.x; e < 4096; e += 256) {
        float run = 0.f;
        size_t base = base0 + e;
        #pragma unroll
        for (int c = 0; c < NCHUNK; c++) {
            float t = g_kv[base + (size_t)c * 4096];
            g_kv[base + (size_t)c * 4096] = run;
            run += t;
        }
    }
}

// ---------------------------------------------------------------------------
// Per-(b,h,chunk) output: y = Q @ S + (Q K^T (.) tril) @ V
// ---------------------------------------------------------------------------
__global__ __launch_bounds__(256) void chunk_out_kernel()
{
    __shared__ float Qs[64][64];   // Qs[i][t]  (transposed)
    __shared__ float Bs[64][64];   // S natural -> K^T [i][s] -> V natural
    __shared__ float Ps[64][64];   // Ps[s][t]

    const int blk = blockIdx.x;
    const int c   = blk & 31;
    const int bh  = blk >> 5;
    const int h   = bh & 15;
    const int b   = bh >> 4;
    const int tid = threadIdx.x;
    const int t0  = (tid >> 4) * 4;
    const int j0  = (tid & 15) * 4;
    const int ct0 = c * CHUNK;

    for (int idx = tid; idx < 64*16; idx += 256) {
        int r = idx >> 4, c4 = idx & 15;
        size_t base = ((size_t)(b*L_SEQ + ct0 + r)) * TRIPLE + h*DHEAD + c4*4;
        float4 q4 = *(const float4*)(g_qkv + base);
        Qs[c4*4+0][r] = q4.x; Qs[c4*4+1][r] = q4.y;
        Qs[c4*4+2][r] = q4.z; Qs[c4*4+3][r] = q4.w;
        *(float4*)&Bs[r][c4*4] =
            *(const float4*)(g_kv + (size_t)blk * 4096 + r*64 + c4*4);
    }
    __syncthreads();

    float acc[4][4] = {};
    #pragma unroll 8
    for (int i = 0; i < 64; i++) {
        float q4[4], s4[4];
        *(float4*)q4 = *(const float4*)&Qs[i][t0];
        *(float4*)s4 = *(const float4*)&Bs[i][j0];
        #pragma unroll
        for (int tt = 0; tt < 4; tt++)
            #pragma unroll
            for (int jj = 0; jj < 4; jj++)
                acc[tt][jj] = fmaf(q4[tt], s4[jj], acc[tt][jj]);
    }
    __syncthreads();

    for (int idx = tid; idx < 64*16; idx += 256) {
        int r = idx >> 4, c4 = idx & 15;
        size_t base = ((size_t)(b*L_SEQ + ct0 + r)) * TRIPLE + 1024 + h*DHEAD + c4*4;
        float4 k4 = *(const float4*)(g_qkv + base);
        Bs[c4*4+0][r] = k4.x * 0.125f; Bs[c4*4+1][r] = k4.y * 0.125f;
        Bs[c4*4+2][r] = k4.z * 0.125f; Bs[c4*4+3][r] = k4.w * 0.125f;
    }
    __syncthreads();

    {
        float pacc[4][4] = {};
        #pragma unroll 8
        for (int i = 0; i < 64; i++) {
            float k4[4], q4[4];
            *(float4*)k4 = *(const float4*)&Bs[i][t0];   // K^T: [i][s]
            *(float4*)q4 = *(const float4*)&Qs[i][j0];   // Q^T: [i][t]
            #pragma unroll
            for (int ss = 0; ss < 4; ss++)
                #pragma unroll
                for (int tt = 0; tt < 4; tt++)
                    pacc[ss][tt] = fmaf(k4[ss], q4[tt], pacc[ss][tt]);
        }
        #pragma unroll
        for (int ss = 0; ss < 4; ss++) {
            int s = t0 + ss;
            float4 o;
            o.x = (j0+0 >= s) ? pacc[ss][0] : 0.f;
            o.y = (j0+1 >= s) ? pacc[ss][1] : 0.f;
            o.z = (j0+2 >= s) ? pacc[ss][2] : 0.f;
            o.w = (j0+3 >= s) ? pacc[ss][3] : 0.f;
            *(float4*)&Ps[s][j0] = o;
        }
    }
    __syncthreads();

    for (int idx = tid; idx < 64*16; idx += 256) {
        int r = idx >> 4, c4 = idx & 15;
        size_t base = ((size_t)(b*L_SEQ + ct0 + r)) * TRIPLE + 2048 + h*DHEAD + c4*4;
        *(float4*)&Bs[r][c4*4] = *(const float4*)(g_qkv + base);
    }
    __syncthreads();

    #pragma unroll 8
    for (int s = 0; s < 64; s++) {
        float p4[4], v4[4];
        *(float4*)p4 = *(const float4*)&Ps[s][t0];
        *(float4*)v4 = *(const float4*)&Bs[s][j0];
        #pragma unroll
        for (int tt = 0; tt < 4; tt++)
            #pragma unroll
            for (int jj = 0; jj < 4; jj++)
                acc[tt][jj] = fmaf(p4[tt], v4[jj], acc[tt][jj]);
    }

    #pragma unroll
    for (int tt = 0; tt < 4; tt++) {
        size_t row = (size_t)(b*L_SEQ + ct0 + t0 + tt);
        *(float4*)(g_y + row * D_MODEL + h*DHEAD + j0) =
            make_float4(acc[tt][0], acc[tt][1], acc[tt][2], acc[tt][3]);
    }
}

// ---------------------------------------------------------------------------
extern "C" void kernel_launch(void* const* d_in, const int* in_sizes, int n_in,
                              void* d_out, int out_size)
{
    const float* x      = (const float*)d_in[0];
    const float* Wqkv_w = (const float*)d_in[1];
    const float* Wqkv_b = (const float*)d_in[2];
    const float* out_w  = (const float*)d_in[3];
    const float* out_b  = (const float*)d_in[4];
    float* out = (float*)d_out;

    // 0) split-convert inputs/weights to bf16 hi/lo
    cvt_x <<<MROWS*D_MODEL/4/256,   256>>>(x);
    cvt_w <<<TRIPLE*D_MODEL/4/256,  256>>>(Wqkv_w);
    cvt_ow<<<D_MODEL*D_MODEL/4/256, 256>>>(out_w);

    // 1) QKV projection (tensor cores): g_qkv = x @ Wqkv_w^T + b
    gemm_qkv_bf16<<<dim3(TRIPLE/128, MROWS/128), 256>>>(Wqkv_b);

    // 2) Per-chunk KV = K^T V
    chunk_kv_kernel<<<1024, 256>>>();

    // 3) Exclusive prefix over chunks -> inter-chunk states S
    prefix_kernel<<<32, 256>>>();

    // 4) Per-chunk output: y = Q S + (Q K^T . tril) V
    chunk_out_kernel<<<1024, 256>>>();

    // 5) split-convert y, then output projection (tensor cores)
    cvt_y<<<MROWS*D_MODEL/4/256, 256>>>();
    gemm_out_bf16<<<dim3(D_MODEL/128, MROWS/128), 256>>>(out_b, out);
}

// round 4
// speedup vs baseline: 1.7717x; 1.0751x over previous
#include <cuda_runtime.h>
#include <cuda_bf16.h>
#include <cstdint>

// Problem constants: B=2, L=2048, D=1024, H=16, d=64
#define L_SEQ   2048
#define D_MODEL 1024
#define NHEADS  16
#define DHEAD   64
#define CHUNK   64
#define NCHUNK  32
#define MROWS   4096            // B * L
#define TRIPLE  3072            // 3 * D

// fp32 scratch
__device__ float g_qkv[(size_t)MROWS * TRIPLE];            // [B*L, 3D]
__device__ float g_kv [(size_t)1024 * 4096];               // [B*H*NC, 64*64]

// bf16 split planes
__device__ __nv_bfloat16 g_xh[(size_t)MROWS * D_MODEL];
__device__ __nv_bfloat16 g_xl[(size_t)MROWS * D_MODEL];
__device__ __nv_bfloat16 g_wh[(size_t)TRIPLE * D_MODEL];
__device__ __nv_bfloat16 g_wl[(size_t)TRIPLE * D_MODEL];
__device__ __nv_bfloat16 g_yh[(size_t)MROWS * D_MODEL];
__device__ __nv_bfloat16 g_yl[(size_t)MROWS * D_MODEL];
__device__ __nv_bfloat16 g_owh[(size_t)D_MODEL * D_MODEL];
__device__ __nv_bfloat16 g_owl[(size_t)D_MODEL * D_MODEL];

// ---------------------------------------------------------------------------
// fp32 -> (bf16 hi, bf16 lo) split conversion, float4-vectorized.
// ---------------------------------------------------------------------------
__device__ __forceinline__ void cvt_body(const float* __restrict__ in,
                                         __nv_bfloat16* __restrict__ hi,
                                         __nv_bfloat16* __restrict__ lo,
                                         int n4)
{
    int i = blockIdx.x * blockDim.x + threadIdx.x;
    if (i >= n4) return;
    float4 v = ((const float4*)in)[i];
    __nv_bfloat16 h0 = __float2bfloat16(v.x);
    __nv_bfloat16 h1 = __float2bfloat16(v.y);
    __nv_bfloat16 h2 = __float2bfloat16(v.z);
    __nv_bfloat16 h3 = __float2bfloat16(v.w);
    __nv_bfloat162 hh0; hh0.x = h0; hh0.y = h1;
    __nv_bfloat162 hh1; hh1.x = h2; hh1.y = h3;
    __nv_bfloat162 ll0, ll1;
    ll0.x = __float2bfloat16(v.x - __bfloat162float(h0));
    ll0.y = __float2bfloat16(v.y - __bfloat162float(h1));
    ll1.x = __float2bfloat16(v.z - __bfloat162float(h2));
    ll1.y = __float2bfloat16(v.w - __bfloat162float(h3));
    ((__nv_bfloat162*)hi)[i*2+0] = hh0;
    ((__nv_bfloat162*)hi)[i*2+1] = hh1;
    ((__nv_bfloat162*)lo)[i*2+0] = ll0;
    ((__nv_bfloat162*)lo)[i*2+1] = ll1;
}

__global__ void cvt_x   (const float* __restrict__ in) { cvt_body(in,  g_xh,  g_xl,  MROWS*D_MODEL/4); }
__global__ void cvt_w   (const float* __restrict__ in) { cvt_body(in,  g_wh,  g_wl,  TRIPLE*D_MODEL/4); }
__global__ void cvt_ow  (const float* __restrict__ in) { cvt_body(in,  g_owh, g_owl, D_MODEL*D_MODEL/4); }

// ---------------------------------------------------------------------------
// bf16-split tensor-core GEMM (NT): C[M,N] = A[M,K] @ B[N,K]^T + bias[N]
// Software-pipelined: next k-tile prefetched to registers during MMA compute.
// 128x128 block tile, BK=32, 256 threads, 8 warps (2x4), warp tile 64x32.
// ---------------------------------------------------------------------------
#define SP 40   // smem row stride in halves (padded)

__device__ __forceinline__ void mma16816(float* d, const unsigned* a, const unsigned* b)
{
    asm volatile(
        "mma.sync.aligned.m16n8k16.row.col.f32.bf16.bf16.f32 "
        "{%0,%1,%2,%3}, {%4,%5,%6,%7}, {%8,%9}, {%0,%1,%2,%3};\n"
        : "+f"(d[0]), "+f"(d[1]), "+f"(d[2]), "+f"(d[3])
        : "r"(a[0]), "r"(a[1]), "r"(a[2]), "r"(a[3]), "r"(b[0]), "r"(b[1]));
}

template<int M, int N, int K>
__device__ __forceinline__ void gemm_body(
    const __nv_bfloat16* __restrict__ Ahi, const __nv_bfloat16* __restrict__ Alo,
    const __nv_bfloat16* __restrict__ Bhi, const __nv_bfloat16* __restrict__ Blo,
    const float* __restrict__ bias, float* __restrict__ C)
{
    __shared__ __nv_bfloat16 sAh[128*SP];
    __shared__ __nv_bfloat16 sAl[128*SP];
    __shared__ __nv_bfloat16 sBh[128*SP];
    __shared__ __nv_bfloat16 sBl[128*SP];

    const int tid  = threadIdx.x;
    const int warp = tid >> 5;
    const int lane = tid & 31;
    const int wm   = warp & 1;          // 0..1 -> 64-row half
    const int wn   = warp >> 1;         // 0..3 -> 32-col quarter
    const int g    = lane >> 2;         // 0..7
    const int t    = lane & 3;          // 0..3
    const int m0   = blockIdx.y * 128;
    const int n0   = blockIdx.x * 128;

    // per-thread load coordinates (2 chunks of uint4 per plane per tile)
    int row0 = (tid + 0)   >> 2, q0 = (tid + 0)   & 3;
    int row1 = (tid + 256) >> 2, q1 = (tid + 256) & 3;
    const size_t gA0 = (size_t)(m0 + row0) * K + q0*8;
    const size_t gA1 = (size_t)(m0 + row1) * K + q1*8;
    const size_t gB0 = (size_t)(n0 + row0) * K + q0*8;
    const size_t gB1 = (size_t)(n0 + row1) * K + q1*8;
    const int so0 = row0*SP + q0*8;
    const int so1 = row1*SP + q1*8;

    float acc[4][4][4];
    #pragma unroll
    for (int mt = 0; mt < 4; mt++)
        #pragma unroll
        for (int nt = 0; nt < 4; nt++)
            #pragma unroll
            for (int r = 0; r < 4; r++) acc[mt][nt][r] = 0.f;

    uint4 rah0, rah1, ral0, ral1, rbh0, rbh1, rbl0, rbl1;

    // prologue: prefetch tile 0
    rah0 = *(const uint4*)&Ahi[gA0]; rah1 = *(const uint4*)&Ahi[gA1];
    ral0 = *(const uint4*)&Alo[gA0]; ral1 = *(const uint4*)&Alo[gA1];
    rbh0 = *(const uint4*)&Bhi[gB0]; rbh1 = *(const uint4*)&Bhi[gB1];
    rbl0 = *(const uint4*)&Blo[gB0]; rbl1 = *(const uint4*)&Blo[gB1];

    for (int k0 = 0; k0 < K; k0 += 32) {
        // commit prefetched tile to smem
        *(uint4*)&sAh[so0] = rah0; *(uint4*)&sAh[so1] = rah1;
        *(uint4*)&sAl[so0] = ral0; *(uint4*)&sAl[so1] = ral1;
        *(uint4*)&sBh[so0] = rbh0; *(uint4*)&sBh[so1] = rbh1;
        *(uint4*)&sBl[so0] = rbl0; *(uint4*)&sBl[so1] = rbl1;
        __syncthreads();

        // prefetch next tile (hidden behind MMA compute below)
        if (k0 + 32 < K) {
            int kn = k0 + 32;
            rah0 = *(const uint4*)&Ahi[gA0 + kn]; rah1 = *(const uint4*)&Ahi[gA1 + kn];
            ral0 = *(const uint4*)&Alo[gA0 + kn]; ral1 = *(const uint4*)&Alo[gA1 + kn];
            rbh0 = *(const uint4*)&Bhi[gB0 + kn]; rbh1 = *(const uint4*)&Bhi[gB1 + kn];
            rbl0 = *(const uint4*)&Blo[gB0 + kn]; rbl1 = *(const uint4*)&Blo[gB1 + kn];
        }

        #pragma unroll
        for (int ks = 0; ks < 32; ks += 16) {
            unsigned ah[4][4], al[4][4], bh[4][2], bl[4][2];
            #pragma unroll
            for (int mt = 0; mt < 4; mt++) {
                int base = (wm*64 + mt*16 + g)*SP + ks + 2*t;
                ah[mt][0] = *(const unsigned*)&sAh[base];
                ah[mt][1] = *(const unsigned*)&sAh[base + 8*SP];
                ah[mt][2] = *(const unsigned*)&sAh[base + 8];
                ah[mt][3] = *(const unsigned*)&sAh[base + 8*SP + 8];
                al[mt][0] = *(const unsigned*)&sAl[base];
                al[mt][1] = *(const unsigned*)&sAl[base + 8*SP];
                al[mt][2] = *(const unsigned*)&sAl[base + 8];
                al[mt][3] = *(const unsigned*)&sAl[base + 8*SP + 8];
            }
            #pragma unroll
            for (int nt = 0; nt < 4; nt++) {
                int base = (wn*32 + nt*8 + g)*SP + ks + 2*t;
                bh[nt][0] = *(const unsigned*)&sBh[base];
                bh[nt][1] = *(const unsigned*)&sBh[base + 8];
                bl[nt][0] = *(const unsigned*)&sBl[base];
                bl[nt][1] = *(const unsigned*)&sBl[base + 8];
            }
            #pragma unroll
            for (int mt = 0; mt < 4; mt++)
                #pragma unroll
                for (int nt = 0; nt < 4; nt++) {
                    mma16816(acc[mt][nt], ah[mt], bh[nt]);  // hi*hi
                    mma16816(acc[mt][nt], ah[mt], bl[nt]);  // hi*lo
                    mma16816(acc[mt][nt], al[mt], bh[nt]);  // lo*hi
                }
        }
        __syncthreads();
    }

    // ---- epilogue: C[r][c] = acc + bias[c], float2 stores ----
    #pragma unroll
    for (int mt = 0; mt < 4; mt++) {
        int r = m0 + wm*64 + mt*16 + g;
        #pragma unroll
        for (int nt = 0; nt < 4; nt++) {
            int c = n0 + wn*32 + nt*8 + 2*t;
            float b0 = bias[c], b1 = bias[c+1];
            float2 o0 = make_float2(acc[mt][nt][0] + b0, acc[mt][nt][1] + b1);
            float2 o1 = make_float2(acc[mt][nt][2] + b0, acc[mt][nt][3] + b1);
            *(float2*)&C[(size_t)r * N + c]       = o0;
            *(float2*)&C[(size_t)(r+8) * N + c]   = o1;
        }
    }
}

__global__ __launch_bounds__(256,1) void gemm_qkv_bf16(const float* __restrict__ bias)
{
    gemm_body<MROWS, TRIPLE, D_MODEL>(g_xh, g_xl, g_wh, g_wl, bias, g_qkv);
}

__global__ __launch_bounds__(256,1) void gemm_out_bf16(const float* __restrict__ bias,
                                                       float* __restrict__ C)
{
    gemm_body<MROWS, D_MODEL, D_MODEL>(g_yh, g_yl, g_owh, g_owl, bias, C);
}

// ---------------------------------------------------------------------------
// Per-(b,h,chunk): KV = K_c^T V_c  (64x64), K pre-scaled by 1/sqrt(d)=0.125
// ---------------------------------------------------------------------------
__global__ __launch_bounds__(256) void chunk_kv_kernel()
{
    __shared__ float Ks[64][64];
    __shared__ float Vs[64][64];
    const int blk = blockIdx.x;            // bh*32 + c
    const int c   = blk & 31;
    const int bh  = blk >> 5;
    const int h   = bh & 15;
    const int b   = bh >> 4;
    const int tid = threadIdx.x;
    const int t0g = c * CHUNK;

    for (int idx = tid; idx < 64*16; idx += 256) {
        int r = idx >> 4, c4 = idx & 15;
        size_t base = ((size_t)(b*L_SEQ + t0g + r)) * TRIPLE + h*DHEAD + c4*4;
        float4 k4 = *(const float4*)(g_qkv + base + 1024);
        float4 v4 = *(const float4*)(g_qkv + base + 2048);
        k4.x *= 0.125f; k4.y *= 0.125f; k4.z *= 0.125f; k4.w *= 0.125f;
        *(float4*)&Ks[r][c4*4] = k4;
        *(float4*)&Vs[r][c4*4] = v4;
    }
    __syncthreads();

    const int i0 = (tid >> 4) * 4;
    const int j0 = (tid & 15) * 4;
    float acc[4][4] = {};
    #pragma unroll 8
    for (int t = 0; t < 64; t++) {
        float k4[4], v4[4];
        *(float4*)k4 = *(const float4*)&Ks[t][i0];
        *(float4*)v4 = *(const float4*)&Vs[t][j0];
        #pragma unroll
        for (int ii = 0; ii < 4; ii++)
            #pragma unroll
            for (int jj = 0; jj < 4; jj++)
                acc[ii][jj] = fmaf(k4[ii], v4[jj], acc[ii][jj]);
    }
    float* outp = g_kv + (size_t)blk * 4096;
    #pragma unroll
    for (int ii = 0; ii < 4; ii++)
        *(float4*)(outp + (i0+ii)*64 + j0) =
            make_float4(acc[ii][0], acc[ii][1], acc[ii][2], acc[ii][3]);
}

// ---------------------------------------------------------------------------
// In-place exclusive prefix over chunks: S_c = sum_{c'<c} KV_{c'}
// ---------------------------------------------------------------------------
__global__ __launch_bounds__(256) void prefix_kernel()
{
    const int bh = blockIdx.x;
    const size_t base0 = (size_t)bh * NCHUNK * 4096;
    for (int e = threadIdx.x; e < 4096; e += 256) {
        float run = 0.f;
        size_t base = base0 + e;
        #pragma unroll
        for (int c = 0; c < NCHUNK; c++) {
            float t = g_kv[base + (size_t)c * 4096];
            g_kv[base + (size_t)c * 4096] = run;
            run += t;
        }
    }
}

// ---------------------------------------------------------------------------
// Per-(b,h,chunk) output: y = Q @ S + (Q K^T (.) tril) @ V
// Writes y directly as bf16 hi/lo split planes (fuses the old cvt_y pass).
// ---------------------------------------------------------------------------
__global__ __launch_bounds__(256) void chunk_out_kernel()
{
    __shared__ float Qs[64][64];   // Qs[i][t]  (transposed)
    __shared__ float Bs[64][64];   // S natural -> K^T [i][s] -> V natural
    __shared__ float Ps[64][64];   // Ps[s][t]

    const int blk = blockIdx.x;
    const int c   = blk & 31;
    const int bh  = blk >> 5;
    const int h   = bh & 15;
    const int b   = bh >> 4;
    const int tid = threadIdx.x;
    const int t0  = (tid >> 4) * 4;
    const int j0  = (tid & 15) * 4;
    const int ct0 = c * CHUNK;

    for (int idx = tid; idx < 64*16; idx += 256) {
        int r = idx >> 4, c4 = idx & 15;
        size_t base = ((size_t)(b*L_SEQ + ct0 + r)) * TRIPLE + h*DHEAD + c4*4;
        float4 q4 = *(const float4*)(g_qkv + base);
        Qs[c4*4+0][r] = q4.x; Qs[c4*4+1][r] = q4.y;
        Qs[c4*4+2][r] = q4.z; Qs[c4*4+3][r] = q4.w;
        *(float4*)&Bs[r][c4*4] =
            *(const float4*)(g_kv + (size_t)blk * 4096 + r*64 + c4*4);
    }
    __syncthreads();

    float acc[4][4] = {};
    #pragma unroll 8
    for (int i = 0; i < 64; i++) {
        float q4[4], s4[4];
        *(float4*)q4 = *(const float4*)&Qs[i][t0];
        *(float4*)s4 = *(const float4*)&Bs[i][j0];
        #pragma unroll
        for (int tt = 0; tt < 4; tt++)
            #pragma unroll
            for (int jj = 0; jj < 4; jj++)
                acc[tt][jj] = fmaf(q4[tt], s4[jj], acc[tt][jj]);
    }
    __syncthreads();

    for (int idx = tid; idx < 64*16; idx += 256) {
        int r = idx >> 4, c4 = idx & 15;
        size_t base = ((size_t)(b*L_SEQ + ct0 + r)) * TRIPLE + 1024 + h*DHEAD + c4*4;
        float4 k4 = *(const float4*)(g_qkv + base);
        Bs[c4*4+0][r] = k4.x * 0.125f; Bs[c4*4+1][r] = k4.y * 0.125f;
        Bs[c4*4+2][r] = k4.z * 0.125f; Bs[c4*4+3][r] = k4.w * 0.125f;
    }
    __syncthreads();

    {
        float pacc[4][4] = {};
        #pragma unroll 8
        for (int i = 0; i < 64; i++) {
            float k4[4], q4[4];
            *(float4*)k4 = *(const float4*)&Bs[i][t0];   // K^T: [i][s]
            *(float4*)q4 = *(const float4*)&Qs[i][j0];   // Q^T: [i][t]
            #pragma unroll
            for (int ss = 0; ss < 4; ss++)
                #pragma unroll
                for (int tt = 0; tt < 4; tt++)
                    pacc[ss][tt] = fmaf(k4[ss], q4[tt], pacc[ss][tt]);
        }
        #pragma unroll
        for (int ss = 0; ss < 4; ss++) {
            int s = t0 + ss;
            float4 o;
            o.x = (j0+0 >= s) ? pacc[ss][0] : 0.f;
            o.y = (j0+1 >= s) ? pacc[ss][1] : 0.f;
            o.z = (j0+2 >= s) ? pacc[ss][2] : 0.f;
            o.w = (j0+3 >= s) ? pacc[ss][3] : 0.f;
            *(float4*)&Ps[s][j0] = o;
        }
    }
    __syncthreads();

    for (int idx = tid; idx < 64*16; idx += 256) {
        int r = idx >> 4, c4 = idx & 15;
        size_t base = ((size_t)(b*L_SEQ + ct0 + r)) * TRIPLE + 2048 + h*DHEAD + c4*4;
        *(float4*)&Bs[r][c4*4] = *(const float4*)(g_qkv + base);
    }
    __syncthreads();

    #pragma unroll 8
    for (int s = 0; s < 64; s++) {
        float p4[4], v4[4];
        *(float4*)p4 = *(const float4*)&Ps[s][t0];
        *(float4*)v4 = *(const float4*)&Bs[s][j0];
        #pragma unroll
        for (int tt = 0; tt < 4; tt++)
            #pragma unroll
            for (int jj = 0; jj < 4; jj++)
                acc[tt][jj] = fmaf(p4[tt], v4[jj], acc[tt][jj]);
    }

    // Store y as bf16 hi/lo split (for the output GEMM)
    #pragma unroll
    for (int tt = 0; tt < 4; tt++) {
        size_t off = ((size_t)(b*L_SEQ + ct0 + t0 + tt)) * D_MODEL + h*DHEAD + j0;
        __nv_bfloat162 h01, h23, l01, l23;
        h01.x = __float2bfloat16(acc[tt][0]);
        h01.y = __float2bfloat16(acc[tt][1]);
        h23.x = __float2bfloat16(acc[tt][2]);
        h23.y = __float2bfloat16(acc[tt][3]);
        l01.x = __float2bfloat16(acc[tt][0] - __bfloat162float(h01.x));
        l01.y = __float2bfloat16(acc[tt][1] - __bfloat162float(h01.y));
        l23.x = __float2bfloat16(acc[tt][2] - __bfloat162float(h23.x));
        l23.y = __float2bfloat16(acc[tt][3] - __bfloat162float(h23.y));
        *(__nv_bfloat162*)&g_yh[off]     = h01;
        *(__nv_bfloat162*)&g_yh[off + 2] = h23;
        *(__nv_bfloat162*)&g_yl[off]     = l01;
        *(__nv_bfloat162*)&g_yl[off + 2] = l23;
    }
}

// ---------------------------------------------------------------------------
extern "C" void kernel_launch(void* const* d_in, const int* in_sizes, int n_in,
                              void* d_out, int out_size)
{
    const float* x      = (const float*)d_in[0];
    const float* Wqkv_w = (const float*)d_in[1];
    const float* Wqkv_b = (const float*)d_in[2];
    const float* out_w  = (const float*)d_in[3];
    const float* out_b  = (const float*)d_in[4];
    float* out = (float*)d_out;

    // 0) split-convert inputs/weights to bf16 hi/lo
    cvt_x <<<MROWS*D_MODEL/4/256,   256>>>(x);
    cvt_w <<<TRIPLE*D_MODEL/4/256,  256>>>(Wqkv_w);
    cvt_ow<<<D_MODEL*D_MODEL/4/256, 256>>>(out_w);

    // 1) QKV projection (tensor cores, pipelined): g_qkv = x @ Wqkv_w^T + b
    gemm_qkv_bf16<<<dim3(TRIPLE/128, MROWS/128), 256>>>(Wqkv_b);

    // 2) Per-chunk KV = K^T V
    chunk_kv_kernel<<<1024, 256>>>();

    // 3) Exclusive prefix over chunks -> inter-chunk states S
    prefix_kernel<<<32, 256>>>();

    // 4) Per-chunk output: y = Q S + (Q K^T . tril) V  (writes bf16 split)
    chunk_out_kernel<<<1024, 256>>>();

    // 5) Output projection (tensor cores, pipelined)
    gemm_out_bf16<<<dim3(D_MODEL/128, MROWS/128), 256>>>(out_b, out);
}

// round 6
// speedup vs baseline: 2.0448x; 1.1542x over previous
#include <cuda_runtime.h>
#include <cuda_bf16.h>
#include <cstdint>

// Problem constants: B=2, L=2048, D=1024, H=16, d=64
#define L_SEQ   2048
#define D_MODEL 1024
#define NHEADS  16
#define DHEAD   64
#define CHUNK   64
#define NCHUNK  32
#define MROWS   4096            // B * L
#define TRIPLE  3072            // 3 * D

// fp32 scratch
__device__ float g_qkv[(size_t)MROWS * TRIPLE];            // [B*L, 3D]
__device__ float g_kv [(size_t)1024 * 4096];               // [B*H*NC, 64*64]

// bf16 split planes (row-major, K contiguous)
__device__ __nv_bfloat16 g_xh[(size_t)MROWS * D_MODEL];
__device__ __nv_bfloat16 g_xl[(size_t)MROWS * D_MODEL];
__device__ __nv_bfloat16 g_wh[(size_t)TRIPLE * D_MODEL];
__device__ __nv_bfloat16 g_wl[(size_t)TRIPLE * D_MODEL];
__device__ __nv_bfloat16 g_yh[(size_t)MROWS * D_MODEL];
__device__ __nv_bfloat16 g_yl[(size_t)MROWS * D_MODEL];
__device__ __nv_bfloat16 g_owh[(size_t)D_MODEL * D_MODEL];
__device__ __nv_bfloat16 g_owl[(size_t)D_MODEL * D_MODEL];

// ---------------------------------------------------------------------------
// helpers
// ---------------------------------------------------------------------------
__device__ __forceinline__ uint32_t smem_u32(const void* p) {
    uint32_t a;
    asm("{ .reg .u64 t; cvta.to.shared.u64 t, %1; cvt.u32.u64 %0, t; }"
        : "=r"(a) : "l"(p));
    return a;
}

#define CP_ASYNC16(dst_u32, src_ptr) \
    asm volatile("cp.async.cg.shared.global [%0], [%1], 16;" \
                 :: "r"(dst_u32), "l"(src_ptr))
#define CP_COMMIT()  asm volatile("cp.async.commit_group;" ::: "memory")
#define CP_WAIT0()   asm volatile("cp.async.wait_group 0;"  ::: "memory")

__device__ __forceinline__ void ldmx4(unsigned* r, uint32_t addr) {
    asm volatile("ldmatrix.sync.aligned.m8n8.x4.shared.b16 {%0,%1,%2,%3}, [%4];"
                 : "=r"(r[0]), "=r"(r[1]), "=r"(r[2]), "=r"(r[3]) : "r"(addr));
}
__device__ __forceinline__ void ldmx2(unsigned* r, uint32_t addr) {
    asm volatile("ldmatrix.sync.aligned.m8n8.x2.shared.b16 {%0,%1}, [%2];"
                 : "=r"(r[0]), "=r"(r[1]) : "r"(addr));
}

__device__ __forceinline__ void mma16816(float* d, const unsigned* a, const unsigned* b)
{
    asm volatile(
        "mma.sync.aligned.m16n8k16.row.col.f32.bf16.bf16.f32 "
        "{%0,%1,%2,%3}, {%4,%5,%6,%7}, {%8,%9}, {%0,%1,%2,%3};\n"
        : "+f"(d[0]), "+f"(d[1]), "+f"(d[2]), "+f"(d[3])
        : "r"(a[0]), "r"(a[1]), "r"(a[2]), "r"(a[3]), "r"(b[0]), "r"(b[1]));
}

// ---------------------------------------------------------------------------
// fp32 -> (bf16 hi, bf16 lo) split conversion, float4-vectorized.
// ---------------------------------------------------------------------------
__device__ __forceinline__ void cvt_body(const float* __restrict__ in,
                                         __nv_bfloat16* __restrict__ hi,
                                         __nv_bfloat16* __restrict__ lo,
                                         int n4)
{
    int i = blockIdx.x * blockDim.x + threadIdx.x;
    if (i >= n4) return;
    float4 v = ((const float4*)in)[i];
    __nv_bfloat16 h0 = __float2bfloat16(v.x);
    __nv_bfloat16 h1 = __float2bfloat16(v.y);
    __nv_bfloat16 h2 = __float2bfloat16(v.z);
    __nv_bfloat16 h3 = __float2bfloat16(v.w);
    __nv_bfloat162 hh0; hh0.x = h0; hh0.y = h1;
    __nv_bfloat162 hh1; hh1.x = h2; hh1.y = h3;
    __nv_bfloat162 ll0, ll1;
    ll0.x = __float2bfloat16(v.x - __bfloat162float(h0));
    ll0.y = __float2bfloat16(v.y - __bfloat162float(h1));
    ll1.x = __float2bfloat16(v.z - __bfloat162float(h2));
    ll1.y = __float2bfloat16(v.w - __bfloat162float(h3));
    ((__nv_bfloat162*)hi)[i*2+0] = hh0;
    ((__nv_bfloat162*)hi)[i*2+1] = hh1;
    ((__nv_bfloat162*)lo)[i*2+0] = ll0;
    ((__nv_bfloat162*)lo)[i*2+1] = ll1;
}

__global__ void cvt_x (const float* __restrict__ in) { cvt_body(in, g_xh,  g_xl,  MROWS*D_MODEL/4); }
__global__ void cvt_w (const float* __restrict__ in) { cvt_body(in, g_wh,  g_wl,  TRIPLE*D_MODEL/4); }
__global__ void cvt_ow(const float* __restrict__ in) { cvt_body(in, g_owh, g_owl, D_MODEL*D_MODEL/4); }

// ---------------------------------------------------------------------------
// bf16-split tensor-core GEMM (NT): C[M,N] = A[M,K] @ B[N,K]^T + bias[N]
// 128x128 tile, BK=32, 256 threads, 8 warps (2x4), warp tile 64x32.
// cp.async global loads, ldmatrix fragment loads, 2 CTAs/SM.
// ---------------------------------------------------------------------------
#define SP 40   // smem row stride in halves (80B; conflict-free for ldmatrix)

template<int M, int N, int K>
__device__ __forceinline__ void gemm_body(
    const __nv_bfloat16* __restrict__ Ahi, const __nv_bfloat16* __restrict__ Alo,
    const __nv_bfloat16* __restrict__ Bhi, const __nv_bfloat16* __restrict__ Blo,
    const float* __restrict__ bias, float* __restrict__ C)
{
    __shared__ __nv_bfloat16 sAh[128*SP];
    __shared__ __nv_bfloat16 sAl[128*SP];
    __shared__ __nv_bfloat16 sBh[128*SP];
    __shared__ __nv_bfloat16 sBl[128*SP];

    const int tid  = threadIdx.x;
    const int warp = tid >> 5;
    const int lane = tid & 31;
    const int wm   = warp & 1;          // 0..1 -> 64-row half
    const int wn   = warp >> 1;         // 0..3 -> 32-col quarter
    const int g    = lane >> 2;         // 0..7
    const int t    = lane & 3;          // 0..3
    const int m0   = blockIdx.y * 128;
    const int n0   = blockIdx.x * 128;

    const uint32_t uAh = smem_u32(sAh), uAl = smem_u32(sAl);
    const uint32_t uBh = smem_u32(sBh), uBl = smem_u32(sBl);

    // cp.async coordinates: 2 chunks of 16B per plane per thread
    const int row0 = (tid + 0)   >> 2, q0 = (tid + 0)   & 3;
    const int row1 = (tid + 256) >> 2, q1 = (tid + 256) & 3;
    const size_t gA0 = (size_t)(m0 + row0) * K + q0*8;
    const size_t gA1 = (size_t)(m0 + row1) * K + q1*8;
    const size_t gB0 = (size_t)(n0 + row0) * K + q0*8;
    const size_t gB1 = (size_t)(n0 + row1) * K + q1*8;
    const uint32_t so0 = (uint32_t)(row0*SP + q0*8) * 2;
    const uint32_t so1 = (uint32_t)(row1*SP + q1*8) * 2;

    // ldmatrix per-lane addresses (halves -> bytes)
    const int lrow = lane & 7;
    const int sel  = lane >> 3;               // 0..3 for x4
    // A x4: matrices {(r,k),(r+8,k),(r,k+8),(r+8,k+8)}
    const int a_r  = (sel & 1) * 8 + lrow;
    const int a_k  = (sel >> 1) * 8;
    // B x2: matrices {(n,k),(n,k+8)}; lanes>=16 mirror lanes 0..15
    const int b_r  = lrow;
    const int b_k  = (sel & 1) * 8;

    float acc[4][4][4];
    #pragma unroll
    for (int mt = 0; mt < 4; mt++)
        #pragma unroll
        for (int nt = 0; nt < 4; nt++)
            #pragma unroll
            for (int r = 0; r < 4; r++) acc[mt][nt][r] = 0.f;

    for (int k0 = 0; k0 < K; k0 += 32) {
        // async loads: 4 planes x 2 chunks
        CP_ASYNC16(uAh + so0, &Ahi[gA0 + k0]); CP_ASYNC16(uAh + so1, &Ahi[gA1 + k0]);
        CP_ASYNC16(uAl + so0, &Alo[gA0 + k0]); CP_ASYNC16(uAl + so1, &Alo[gA1 + k0]);
        CP_ASYNC16(uBh + so0, &Bhi[gB0 + k0]); CP_ASYNC16(uBh + so1, &Bhi[gB1 + k0]);
        CP_ASYNC16(uBl + so0, &Blo[gB0 + k0]); CP_ASYNC16(uBl + so1, &Blo[gB1 + k0]);
        CP_COMMIT();
        CP_WAIT0();
        __syncthreads();

        #pragma unroll
        for (int ks = 0; ks < 32; ks += 16) {
            unsigned ah[4][4], al[4][4], bh[4][2], bl[4][2];
            #pragma unroll
            for (int mt = 0; mt < 4; mt++) {
                uint32_t off = (uint32_t)((wm*64 + mt*16 + a_r)*SP + ks + a_k) * 2;
                ldmx4(ah[mt], uAh + off);
                ldmx4(al[mt], uAl + off);
            }
            #pragma unroll
            for (int nt = 0; nt < 4; nt++) {
                uint32_t off = (uint32_t)((wn*32 + nt*8 + b_r)*SP + ks + b_k) * 2;
                ldmx2(bh[nt], uBh + off);
                ldmx2(bl[nt], uBl + off);
            }
            #pragma unroll
            for (int mt = 0; mt < 4; mt++)
                #pragma unroll
                for (int nt = 0; nt < 4; nt++) {
                    mma16816(acc[mt][nt], ah[mt], bh[nt]);  // hi*hi
                    mma16816(acc[mt][nt], ah[mt], bl[nt]);  // hi*lo
                    mma16816(acc[mt][nt], al[mt], bh[nt]);  // lo*hi
                }
        }
        __syncthreads();
    }

    // epilogue: C[r][c] = acc + bias[c]
    #pragma unroll
    for (int mt = 0; mt < 4; mt++) {
        int r = m0 + wm*64 + mt*16 + g;
        #pragma unroll
        for (int nt = 0; nt < 4; nt++) {
            int c = n0 + wn*32 + nt*8 + 2*t;
            float b0 = bias[c], b1 = bias[c+1];
            float2 o0 = make_float2(acc[mt][nt][0] + b0, acc[mt][nt][1] + b1);
            float2 o1 = make_float2(acc[mt][nt][2] + b0, acc[mt][nt][3] + b1);
            *(float2*)&C[(size_t)r * N + c]       = o0;
            *(float2*)&C[(size_t)(r+8) * N + c]   = o1;
        }
    }
}

__global__ __launch_bounds__(256, 2) void gemm_qkv_bf16(const float* __restrict__ bias)
{
    gemm_body<MROWS, TRIPLE, D_MODEL>(g_xh, g_xl, g_wh, g_wl, bias, g_qkv);
}

__global__ __launch_bounds__(256, 2) void gemm_out_bf16(const float* __restrict__ bias,
                                                        float* __restrict__ C)
{
    gemm_body<MROWS, D_MODEL, D_MODEL>(g_yh, g_yl, g_owh, g_owl, bias, C);
}

// ---------------------------------------------------------------------------
// Per-(b,h,chunk): KV = K_c^T V_c  (64x64), K pre-scaled by 1/sqrt(d)=0.125
// ---------------------------------------------------------------------------
__global__ __launch_bounds__(256) void chunk_kv_kernel()
{
    __shared__ float Ks[64][64];
    __shared__ float Vs[64][64];
    const int blk = blockIdx.x;            // bh*32 + c
    const int c   = blk & 31;
    const int bh  = blk >> 5;
    const int h   = bh & 15;
    const int b   = bh >> 4;
    const int tid = threadIdx.x;
    const int t0g = c * CHUNK;

    for (int idx = tid; idx < 64*16; idx += 256) {
        int r = idx >> 4, c4 = idx & 15;
        size_t base = ((size_t)(b*L_SEQ + t0g + r)) * TRIPLE + h*DHEAD + c4*4;
        float4 k4 = *(const float4*)(g_qkv + base + 1024);
        float4 v4 = *(const float4*)(g_qkv + base + 2048);
        k4.x *= 0.125f; k4.y *= 0.125f; k4.z *= 0.125f; k4.w *= 0.125f;
        *(float4*)&Ks[r][c4*4] = k4;
        *(float4*)&Vs[r][c4*4] = v4;
    }
    __syncthreads();

    const int i0 = (tid >> 4) * 4;
    const int j0 = (tid & 15) * 4;
    float acc[4][4] = {};
    #pragma unroll 8
    for (int t = 0; t < 64; t++) {
        float k4[4], v4[4];
        *(float4*)k4 = *(const float4*)&Ks[t][i0];
        *(float4*)v4 = *(const float4*)&Vs[t][j0];
        #pragma unroll
        for (int ii = 0; ii < 4; ii++)
            #pragma unroll
            for (int jj = 0; jj < 4; jj++)
                acc[ii][jj] = fmaf(k4[ii], v4[jj], acc[ii][jj]);
    }
    float* outp = g_kv + (size_t)blk * 4096;
    #pragma unroll
    for (int ii = 0; ii < 4; ii++)
        *(float4*)(outp + (i0+ii)*64 + j0) =
            make_float4(acc[ii][0], acc[ii][1], acc[ii][2], acc[ii][3]);
}

// ---------------------------------------------------------------------------
// In-place exclusive prefix over chunks: S_c = sum_{c'<c} KV_{c'}
// ---------------------------------------------------------------------------
__global__ __launch_bounds__(256) void prefix_kernel()
{
    const int bh = blockIdx.x;
    const size_t base0 = (size_t)bh * NCHUNK * 4096;
    for (int e = threadIdx.x; e < 4096; e += 256) {
        float run = 0.f;
        size_t base = base0 + e;
        #pragma unroll
        for (int c = 0; c < NCHUNK; c++) {
            float t = g_kv[base + (size_t)c * 4096];
            g_kv[base + (size_t)c * 4096] = run;
            run += t;
        }
    }
}

// ---------------------------------------------------------------------------
// Per-(b,h,chunk) output: y = Q @ S + (Q K^T (.) tril) @ V
// Writes y directly as bf16 hi/lo split planes.
// ---------------------------------------------------------------------------
__global__ __launch_bounds__(256) void chunk_out_kernel()
{
    __shared__ float Qs[64][64];   // Qs[i][t]  (transposed)
    __shared__ float Bs[64][64];   // S natural -> K^T [i][s] -> V natural
    __shared__ float Ps[64][64];   // Ps[s][t]

    const int blk = blockIdx.x;
    const int c   = blk & 31;
    const int bh  = blk >> 5;
    const int h   = bh & 15;
    const int b   = bh >> 4;
    const int tid = threadIdx.x;
    const int t0  = (tid >> 4) * 4;
    const int j0  = (tid & 15) * 4;
    const int ct0 = c * CHUNK;

    for (int idx = tid; idx < 64*16; idx += 256) {
        int r = idx >> 4, c4 = idx & 15;
        size_t base = ((size_t)(b*L_SEQ + ct0 + r)) * TRIPLE + h*DHEAD + c4*4;
        float4 q4 = *(const float4*)(g_qkv + base);
        Qs[c4*4+0][r] = q4.x; Qs[c4*4+1][r] = q4.y;
        Qs[c4*4+2][r] = q4.z; Qs[c4*4+3][r] = q4.w;
        *(float4*)&Bs[r][c4*4] =
            *(const float4*)(g_kv + (size_t)blk * 4096 + r*64 + c4*4);
    }
    __syncthreads();

    float acc[4][4] = {};
    #pragma unroll 8
    for (int i = 0; i < 64; i++) {
        float q4[4], s4[4];
        *(float4*)q4 = *(const float4*)&Qs[i][t0];
        *(float4*)s4 = *(const float4*)&Bs[i][j0];
        #pragma unroll
        for (int tt = 0; tt < 4; tt++)
            #pragma unroll
            for (int jj = 0; jj < 4; jj++)
                acc[tt][jj] = fmaf(q4[tt], s4[jj], acc[tt][jj]);
    }
    __syncthreads();

    for (int idx = tid; idx < 64*16; idx += 256) {
        int r = idx >> 4, c4 = idx & 15;
        size_t base = ((size_t)(b*L_SEQ + ct0 + r)) * TRIPLE + 1024 + h*DHEAD + c4*4;
        float4 k4 = *(const float4*)(g_qkv + base);
        Bs[c4*4+0][r] = k4.x * 0.125f; Bs[c4*4+1][r] = k4.y * 0.125f;
        Bs[c4*4+2][r] = k4.z * 0.125f; Bs[c4*4+3][r] = k4.w * 0.125f;
    }
    __syncthreads();

    {
        float pacc[4][4] = {};
        #pragma unroll 8
        for (int i = 0; i < 64; i++) {
            float k4[4], q4[4];
            *(float4*)k4 = *(const float4*)&Bs[i][t0];   // K^T: [i][s]
            *(float4*)q4 = *(const float4*)&Qs[i][j0];   // Q^T: [i][t]
            #pragma unroll
            for (int ss = 0; ss < 4; ss++)
                #pragma unroll
                for (int tt = 0; tt < 4; tt++)
                    pacc[ss][tt] = fmaf(k4[ss], q4[tt], pacc[ss][tt]);
        }
        #pragma unroll
        for (int ss = 0; ss < 4; ss++) {
            int s = t0 + ss;
            float4 o;
            o.x = (j0+0 >= s) ? pacc[ss][0] : 0.f;
            o.y = (j0+1 >= s) ? pacc[ss][1] : 0.f;
            o.z = (j0+2 >= s) ? pacc[ss][2] : 0.f;
            o.w = (j0+3 >= s) ? pacc[ss][3] : 0.f;
            *(float4*)&Ps[s][j0] = o;
        }
    }
    __syncthreads();

    for (int idx = tid; idx < 64*16; idx += 256) {
        int r = idx >> 4, c4 = idx & 15;
        size_t base = ((size_t)(b*L_SEQ + ct0 + r)) * TRIPLE + 2048 + h*DHEAD + c4*4;
        *(float4*)&Bs[r][c4*4] = *(const float4*)(g_qkv + base);
    }
    __syncthreads();

    #pragma unroll 8
    for (int s = 0; s < 64; s++) {
        float p4[4], v4[4];
        *(float4*)p4 = *(const float4*)&Ps[s][t0];
        *(float4*)v4 = *(const float4*)&Bs[s][j0];
        #pragma unroll
        for (int tt = 0; tt < 4; tt++)
            #pragma unroll
            for (int jj = 0; jj < 4; jj++)
                acc[tt][jj] = fmaf(p4[tt], v4[jj], acc[tt][jj]);
    }

    // Store y as bf16 hi/lo split (for the output GEMM)
    #pragma unroll
    for (int tt = 0; tt < 4; tt++) {
        size_t off = ((size_t)(b*L_SEQ + ct0 + t0 + tt)) * D_MODEL + h*DHEAD + j0;
        __nv_bfloat162 h01, h23, l01, l23;
        h01.x = __float2bfloat16(acc[tt][0]);
        h01.y = __float2bfloat16(acc[tt][1]);
        h23.x = __float2bfloat16(acc[tt][2]);
        h23.y = __float2bfloat16(acc[tt][3]);
        l01.x = __float2bfloat16(acc[tt][0] - __bfloat162float(h01.x));
        l01.y = __float2bfloat16(acc[tt][1] - __bfloat162float(h01.y));
        l23.x = __float2bfloat16(acc[tt][2] - __bfloat162float(h23.x));
        l23.y = __float2bfloat16(acc[tt][3] - __bfloat162float(h23.y));
        *(__nv_bfloat162*)&g_yh[off]     = h01;
        *(__nv_bfloat162*)&g_yh[off + 2] = h23;
        *(__nv_bfloat162*)&g_yl[off]     = l01;
        *(__nv_bfloat162*)&g_yl[off + 2] = l23;
    }
}

// ---------------------------------------------------------------------------
extern "C" void kernel_launch(void* const* d_in, const int* in_sizes, int n_in,
                              void* d_out, int out_size)
{
    const float* x      = (const float*)d_in[0];
    const float* Wqkv_w = (const float*)d_in[1];
    const float* Wqkv_b = (const float*)d_in[2];
    const float* out_w  = (const float*)d_in[3];
    const float* out_b  = (const float*)d_in[4];
    float* out = (float*)d_out;

    // 0) split-convert inputs/weights to bf16 hi/lo
    cvt_x <<<MROWS*D_MODEL/4/256,   256>>>(x);
    cvt_w <<<TRIPLE*D_MODEL/4/256,  256>>>(Wqkv_w);
    cvt_ow<<<D_MODEL*D_MODEL/4/256, 256>>>(out_w);

    // 1) QKV projection (tensor cores): g_qkv = x @ Wqkv_w^T + b
    gemm_qkv_bf16<<<dim3(TRIPLE/128, MROWS/128), 256>>>(Wqkv_b);

    // 2) Per-chunk KV = K^T V
    chunk_kv_kernel<<<1024, 256>>>();

    // 3) Exclusive prefix over chunks -> inter-chunk states S
    prefix_kernel<<<32, 256>>>();

    // 4) Per-chunk output: y = Q S + (Q K^T . tril) V  (writes bf16 split)
    chunk_out_kernel<<<1024, 256>>>();

    // 5) Output projection (tensor cores)
    gemm_out_bf16<<<dim3(D_MODEL/128, MROWS/128), 256>>>(out_b, out);
}